// round 1
// baseline (speedup 1.0000x reference)
#include <cuda_runtime.h>
#include <math.h>

// Problem dims (fixed)
#define BB 4
#define TT 1024
#define DD 1024
#define HH 16
#define DKV 64
#define FF 4096

// ---------------- scratch (device globals; no allocation allowed) ----------------
__device__ float g_Wt0[DD * DD];
__device__ float g_Wt1[DD * DD];
__device__ float g_Wt2[DD * DD];
__device__ float g_Q  [BB * TT * DD];
__device__ float g_Kb [BB * TT * DD];
__device__ float g_Vb [BB * TT * DD];
__device__ float g_S  [BB * HH * TT * TT];   // 67,108,864 floats (256 MB)
__device__ float g_P  [BB * TT * DD];
__device__ float g_Mo [BB * TT * DD];
__device__ float g_o1 [BB * TT * DD];
__device__ float g_o2 [BB * TT * DD];
__device__ float g_hid[BB * TT * FF];        // 64 MB
__device__ float g_ff [BB * TT * DD];

// ---------------- reductions ----------------
__device__ __forceinline__ float blockReduceSum(float v) {
    __shared__ float sh[32];
    __syncthreads();
    int lane = threadIdx.x & 31, wid = threadIdx.x >> 5;
    #pragma unroll
    for (int o = 16; o; o >>= 1) v += __shfl_xor_sync(0xffffffffu, v, o);
    if (lane == 0) sh[wid] = v;
    __syncthreads();
    if (wid == 0) {
        v = (threadIdx.x < (blockDim.x >> 5)) ? sh[lane] : 0.f;
        #pragma unroll
        for (int o = 16; o; o >>= 1) v += __shfl_xor_sync(0xffffffffu, v, o);
        if (lane == 0) sh[0] = v;
    }
    __syncthreads();
    return sh[0];
}

__device__ __forceinline__ float blockReduceMax(float v) {
    __shared__ float sh[32];
    __syncthreads();
    int lane = threadIdx.x & 31, wid = threadIdx.x >> 5;
    #pragma unroll
    for (int o = 16; o; o >>= 1) v = fmaxf(v, __shfl_xor_sync(0xffffffffu, v, o));
    if (lane == 0) sh[wid] = v;
    __syncthreads();
    if (wid == 0) {
        v = (threadIdx.x < (blockDim.x >> 5)) ? sh[lane] : -1e30f;
        #pragma unroll
        for (int o = 16; o; o >>= 1) v = fmaxf(v, __shfl_xor_sync(0xffffffffu, v, o));
        if (lane == 0) sh[0] = v;
    }
    __syncthreads();
    return sh[0];
}

// ---------------- generic tiled SGEMM ----------------
// C[M,N] = alpha * op(A) @ op(B) (+ bias) (ReLU optional)
//   AT=false: A[m*lda + k]      AT=true: A[k*lda + m]
//   BT=false: B[k*ldb + n]      BT=true: B[n*ldb + k]
// Batched over blockIdx.z: z1=z/zdiv, z2=z%zdiv; per-batch offsets via strides.
template<int BM, int BN, int BK, int TM, int TN, bool AT, bool BT, bool BIAS, bool RELU>
__global__ __launch_bounds__((BM / TM) * (BN / TN))
void gemm_k(const float* __restrict__ A, const float* __restrict__ B,
            const float* __restrict__ bias, float* __restrict__ C,
            int M, int N, int K, int lda, int ldb, int ldc,
            long sA1, long sA2, long sB1, long sB2, long sC1, long sC2,
            int zdiv, float alpha)
{
    constexpr int THREADS = (BM / TM) * (BN / TN);
    __shared__ float As[BK][BM + 4];
    __shared__ float Bs[BK][BN + 4];

    int z  = blockIdx.z;
    int z1 = z / zdiv, z2 = z % zdiv;
    A += z1 * sA1 + z2 * sA2;
    B += z1 * sB1 + z2 * sB2;
    C += z1 * sC1 + z2 * sC2;

    const int row0 = blockIdx.y * BM;
    const int col0 = blockIdx.x * BN;
    const int tid  = threadIdx.x;
    const int tx   = tid % (BN / TN);
    const int ty   = tid / (BN / TN);

    float acc[TM][TN];
    #pragma unroll
    for (int i = 0; i < TM; i++)
        #pragma unroll
        for (int j = 0; j < TN; j++) acc[i][j] = 0.f;

    for (int kk = 0; kk < K; kk += BK) {
        if (!AT) {
            #pragma unroll
            for (int i = tid; i < BM * BK; i += THREADS) {
                int m = i / BK, k = i % BK;
                int gm = row0 + m, gk = kk + k;
                As[k][m] = (gm < M && gk < K) ? A[(long)gm * lda + gk] : 0.f;
            }
        } else {
            #pragma unroll
            for (int i = tid; i < BM * BK; i += THREADS) {
                int k = i / BM, m = i % BM;
                int gm = row0 + m, gk = kk + k;
                As[k][m] = (gm < M && gk < K) ? A[(long)gk * lda + gm] : 0.f;
            }
        }
        if (!BT) {
            #pragma unroll
            for (int i = tid; i < BK * BN; i += THREADS) {
                int k = i / BN, n = i % BN;
                int gn = col0 + n, gk = kk + k;
                Bs[k][n] = (gn < N && gk < K) ? B[(long)gk * ldb + gn] : 0.f;
            }
        } else {
            #pragma unroll
            for (int i = tid; i < BK * BN; i += THREADS) {
                int n = i / BK, k = i % BK;
                int gn = col0 + n, gk = kk + k;
                Bs[k][n] = (gn < N && gk < K) ? B[(long)gn * ldb + gk] : 0.f;
            }
        }
        __syncthreads();

        #pragma unroll
        for (int k = 0; k < BK; k++) {
            float ar[TM], br[TN];
            #pragma unroll
            for (int i = 0; i < TM; i++) ar[i] = As[k][ty * TM + i];
            #pragma unroll
            for (int j = 0; j < TN; j++) br[j] = Bs[k][tx * TN + j];
            #pragma unroll
            for (int i = 0; i < TM; i++)
                #pragma unroll
                for (int j = 0; j < TN; j++)
                    acc[i][j] = fmaf(ar[i], br[j], acc[i][j]);
        }
        __syncthreads();
    }

    #pragma unroll
    for (int i = 0; i < TM; i++) {
        int gm = row0 + ty * TM + i;
        if (gm >= M) continue;
        #pragma unroll
        for (int j = 0; j < TN; j++) {
            int gn = col0 + tx * TN + j;
            if (gn >= N) continue;
            float v = acc[i][j] * alpha;
            if (BIAS) v += bias[gn];
            if (RELU) v = fmaxf(v, 0.f);
            C[(long)gm * ldc + gn] = v;
        }
    }
}

// ---------------- weight repack: (H, D, dk) -> (D, H*dk) ----------------
__global__ void repack_w(const float* __restrict__ W, float* __restrict__ Wt) {
    int idx = blockIdx.x * blockDim.x + threadIdx.x;     // output index
    if (idx >= DD * HH * DKV) return;
    int d = idx / (HH * DKV);
    int r = idx % (HH * DKV);
    int h = r / DKV, k = r % DKV;
    Wt[idx] = W[(long)h * DD * DKV + (long)d * DKV + k];
}

// ---------------- row softmax (rows of length 1024, 256 threads) ----------------
__global__ void softmax_rows(float* __restrict__ S) {
    float* row = S + (long)blockIdx.x * 1024;
    int t = threadIdx.x;
    float x[4];
    float m = -1e30f;
    #pragma unroll
    for (int j = 0; j < 4; j++) { x[j] = row[t + j * 256]; m = fmaxf(m, x[j]); }
    m = blockReduceMax(m);
    float s = 0.f;
    #pragma unroll
    for (int j = 0; j < 4; j++) { x[j] = expf(x[j] - m); s += x[j]; }
    s = blockReduceSum(s);
    float inv = 1.f / s;
    #pragma unroll
    for (int j = 0; j < 4; j++) row[t + j * 256] = x[j] * inv;
}

// ---------------- out = sub_norm(A + R): o - mean(o) - std(o, ddof=1) ----------------
__global__ void add_subnorm(const float* __restrict__ A, const float* __restrict__ R,
                            float* __restrict__ O) {
    long base = (long)blockIdx.x * 1024;
    int t = threadIdx.x;
    float v[4];
    float s = 0.f;
    #pragma unroll
    for (int j = 0; j < 4; j++) { v[j] = A[base + t + j * 256] + R[base + t + j * 256]; s += v[j]; }
    s = blockReduceSum(s);
    float mean = s * (1.f / 1024.f);
    float q = 0.f;
    #pragma unroll
    for (int j = 0; j < 4; j++) { float d = v[j] - mean; q += d * d; }
    q = blockReduceSum(q);
    float sd = sqrtf(q * (1.f / 1023.f));
    #pragma unroll
    for (int j = 0; j < 4; j++) O[base + t + j * 256] = v[j] - mean - sd;
}

// ---------------- host ----------------
extern "C" void kernel_launch(void* const* d_in, const int* in_sizes, int n_in,
                              void* d_out, int out_size) {
    const float* x    = (const float*)d_in[0];
    const float* y    = (const float*)d_in[1];
    const float* Wq1  = (const float*)d_in[2];
    const float* Wk1  = (const float*)d_in[3];
    const float* Wv1  = (const float*)d_in[4];
    const float* Wo1  = (const float*)d_in[5];
    const float* Wq2  = (const float*)d_in[6];
    const float* Wk2  = (const float*)d_in[7];
    const float* Wv2  = (const float*)d_in[8];
    const float* Wo2  = (const float*)d_in[9];
    const float* W_in = (const float*)d_in[10];
    const float* b_in = (const float*)d_in[11];
    const float* W_out= (const float*)d_in[12];
    const float* b_out= (const float*)d_in[13];
    float* out = (float*)d_out;

    float *Wt0, *Wt1, *Wt2, *Q, *K, *V, *S, *P, *M, *o1, *o2, *hid, *ff;
    cudaGetSymbolAddress((void**)&Wt0, g_Wt0);
    cudaGetSymbolAddress((void**)&Wt1, g_Wt1);
    cudaGetSymbolAddress((void**)&Wt2, g_Wt2);
    cudaGetSymbolAddress((void**)&Q,   g_Q);
    cudaGetSymbolAddress((void**)&K,   g_Kb);
    cudaGetSymbolAddress((void**)&V,   g_Vb);
    cudaGetSymbolAddress((void**)&S,   g_S);
    cudaGetSymbolAddress((void**)&P,   g_P);
    cudaGetSymbolAddress((void**)&M,   g_Mo);
    cudaGetSymbolAddress((void**)&o1,  g_o1);
    cudaGetSymbolAddress((void**)&o2,  g_o2);
    cudaGetSymbolAddress((void**)&hid, g_hid);
    cudaGetSymbolAddress((void**)&ff,  g_ff);

    const int MT = BB * TT;             // 4096 rows
    const long Z1A = (long)TT * DD;     // per-batch-b stride in activations
    const long Z2A = DKV;               // per-head stride in activations
    const long Z1S = (long)HH * TT * TT;
    const long Z2S = (long)TT * TT;

    auto run_mha = [&](const float* qsrc, const float* kvsrc,
                       const float* Wq, const float* Wk, const float* Wv, const float* Wo,
                       const float* resid, float* obuf) {
        // 1) repack per-head weights (H,D,dk) -> (D, H*dk)
        repack_w<<<(DD * DD + 255) / 256, 256>>>(Wq, Wt0);
        repack_w<<<(DD * DD + 255) / 256, 256>>>(Wk, Wt1);
        repack_w<<<(DD * DD + 255) / 256, 256>>>(Wv, Wt2);

        // 2) projections: (4096,1024) @ (1024,1024) -> (b,t,h*dk)
        dim3 gp(DD / 128, MT / 128, 1);
        gemm_k<128,128,16,8,8,false,false,false,false><<<gp, 256>>>(
            qsrc, Wt0, nullptr, Q, MT, DD, DD, DD, DD, DD, 0,0,0,0,0,0, 1, 1.f);
        gemm_k<128,128,16,8,8,false,false,false,false><<<gp, 256>>>(
            kvsrc, Wt1, nullptr, K, MT, DD, DD, DD, DD, DD, 0,0,0,0,0,0, 1, 1.f);
        gemm_k<128,128,16,8,8,false,false,false,false><<<gp, 256>>>(
            kvsrc, Wt2, nullptr, V, MT, DD, DD, DD, DD, DD, 0,0,0,0,0,0, 1, 1.f);

        // 3) scores TRANSPOSED: St[b,h,s,t] = (1/8) * K[s,:] . Q[t,:]   (64 batches)
        dim3 gs(TT / 128, TT / 128, BB * HH);
        gemm_k<128,128,16,8,8,false,true,false,false><<<gs, 256>>>(
            K, Q, nullptr, S, TT, TT, DKV, DD, DD, TT,
            Z1A, Z2A, Z1A, Z2A, Z1S, Z2S, HH, 0.125f);

        // 4) softmax over t (= last dim of St) : B*H*T rows
        softmax_rows<<<BB * HH * TT, 256>>>(S);

        // 5) partial[b,t,h,v] = sum_s St[b,h,s,t] * V[b,s,h,v]  (A-transposed GEMM)
        dim3 gv(1, TT / 128, BB * HH);
        gemm_k<128,64,16,8,4,true,false,false,false><<<gv, 256>>>(
            S, V, nullptr, P, TT, DKV, TT, TT, DD, DD,
            Z1S, Z2S, Z1A, Z2A, Z1A, Z2A, HH, 1.f);

        // 6) output projection: (4096,1024) @ Wo(1024,1024)
        gemm_k<128,128,16,8,8,false,false,false,false><<<gp, 256>>>(
            P, Wo, nullptr, M, MT, DD, DD, DD, DD, DD, 0,0,0,0,0,0, 1, 1.f);

        // 7) sub_norm(mha + resid)
        add_subnorm<<<MT, 256>>>(M, resid, obuf);
    };

    // out1 = sub_norm(mha(y,y,y) + y)
    run_mha(y, y, Wq1, Wk1, Wv1, Wo1, y, o1);
    // out2 = sub_norm(mha(y,x,x) + out1)
    run_mha(y, x, Wq2, Wk2, Wv2, Wo2, o1, o2);

    // FFN on y: hid = relu(y @ W_in^T + b_in)
    dim3 gf1(FF / 128, MT / 128, 1);
    gemm_k<128,128,16,8,8,false,true,true,true><<<gf1, 256>>>(
        y, W_in, b_in, hid, MT, FF, DD, DD, DD, FF, 0,0,0,0,0,0, 1, 1.f);
    // ff = hid @ W_out^T + b_out
    dim3 gf2(DD / 128, MT / 128, 1);
    gemm_k<128,128,16,8,8,false,true,true,false><<<gf2, 256>>>(
        hid, W_out, b_out, ff, MT, DD, FF, FF, FF, DD, 0,0,0,0,0,0, 1, 1.f);

    // final: out = sub_norm(ff + out2)
    add_subnorm<<<MT, 256>>>(ff, o2, out);
}

// round 3
// speedup vs baseline: 1.7929x; 1.7929x over previous
#include <cuda_runtime.h>
#include <math.h>
#include <stdint.h>

#define BB 4
#define TT 1024
#define DD 1024
#define HH 16
#define DKV 64
#define FFD 4096

// ---------------- scratch (device globals; no allocation allowed) ----------------
__device__ float g_Wt0[DD * DD];
__device__ float g_Wt1[DD * DD];
__device__ float g_Wt2[DD * DD];
__device__ float g_WoT[DD * DD];
__device__ float g_Q  [BB * TT * DD];
__device__ float g_K  [BB * TT * DD];
__device__ float g_V  [BB * TT * DD];
__device__ float g_Vt [BB * HH * DKV * TT];
__device__ float g_S  [(size_t)BB * HH * TT * TT];   // 256 MB
__device__ float g_dinv[BB * HH * TT];
__device__ float g_P  [BB * TT * DD];
__device__ float g_M  [BB * TT * DD];
__device__ float g_o1 [BB * TT * DD];
__device__ float g_o2 [BB * TT * DD];
__device__ float g_hid[(size_t)BB * TT * FFD];       // 64 MB
__device__ float g_ff [BB * TT * DD];

// ---------------- helpers ----------------
__device__ __forceinline__ uint32_t smem_u32(const void* p) {
    uint32_t a;
    asm("{ .reg .u64 t; cvta.to.shared.u64 t, %1; cvt.u32.u64 %0, t; }" : "=r"(a) : "l"(p));
    return a;
}
__device__ __forceinline__ uint32_t f2tf32(float f) {
    uint32_t u;
    asm("cvt.rna.tf32.f32 %0, %1;" : "=r"(u) : "f"(f));
    return u;
}
__device__ __forceinline__ void split_tf32(float v, uint32_t& hi, uint32_t& lo) {
    uint32_t h = __float_as_uint(v) & 0xffffe000u;   // exact: v = hi + (v-hi)
    hi = h;
    lo = f2tf32(v - __uint_as_float(h));
}
__device__ __forceinline__ void mma_tf32(float* c, const uint32_t* a, const uint32_t* b) {
    asm volatile(
        "mma.sync.aligned.m16n8k8.row.col.f32.tf32.tf32.f32 "
        "{%0,%1,%2,%3}, {%4,%5,%6,%7}, {%8,%9}, {%0,%1,%2,%3};"
        : "+f"(c[0]), "+f"(c[1]), "+f"(c[2]), "+f"(c[3])
        : "r"(a[0]), "r"(a[1]), "r"(a[2]), "r"(a[3]), "r"(b[0]), "r"(b[1]));
}

// ---------------- tf32 mma.sync GEMM: C[M,N] = alpha * A[M,K] @ B[N,K]^T ----------
// A K-major (lda), B K-major (ldb). 3xTF32 split (fp32-grade accuracy).
// BM=128, BK=32, 3-stage cp.async pipeline. Optional exp / bias / relu epilogue.
// Batched over blockIdx.z: z1=z/zdiv, z2=z%zdiv with per-operand strides.
template<int BN, bool BIAS_, bool RELU_, bool EXP_>
__global__ __launch_bounds__(256)
void mma_gemm(const float* __restrict__ A, const float* __restrict__ B,
              const float* __restrict__ bias, float* __restrict__ C,
              int K, int lda, int ldb, int ldc,
              long sA1, long sA2, long sB1, long sB2, long sC1, long sC2,
              int zdiv, float alpha)
{
    constexpr int BM = 128, BK = 32, NST = 3;
    constexpr int WN = BN / 2;         // warp cols (warps: 4 x 2)
    constexpr int NT = WN / 8;         // n-tiles per warp
    constexpr int MT = 2;              // m-tiles per warp (32 rows)
    constexpr int RS = 36;             // smem row stride in floats (bank-friendly)
    constexpr int STG = (BM + BN) * RS;
    constexpr int NLD = (BM + BN) * 8; // float4 loads per stage

    extern __shared__ float sm[];
    const uint32_t smb = smem_u32(sm);

    const int tid  = threadIdx.x;
    const int lane = tid & 31;
    const int wid  = tid >> 5;
    const int wm   = wid >> 1;         // 0..3
    const int wn   = wid & 1;          // 0..1

    const int z  = blockIdx.z;
    const int z1 = z / zdiv, z2 = z % zdiv;
    A += z1 * sA1 + z2 * sA2;
    B += z1 * sB1 + z2 * sB2;
    C += z1 * sC1 + z2 * sC2;

    const int row0 = blockIdx.y * BM;
    const int col0 = blockIdx.x * BN;

    float acc[MT][NT][4];
    #pragma unroll
    for (int i = 0; i < MT; i++)
        #pragma unroll
        for (int j = 0; j < NT; j++)
            #pragma unroll
            for (int q = 0; q < 4; q++) acc[i][j][q] = 0.f;

    const int nch = K / BK;

    auto copy_stage = [&](int s, int c) {
        const int kk = c * BK;
        #pragma unroll
        for (int i = tid; i < NLD; i += 256) {
            const bool isA = (i < BM * 8);
            const int j = isA ? i : (i - BM * 8);
            const int r = j >> 3, c4 = j & 7;
            const float* gp = isA ? (A + (long)(row0 + r) * lda + kk + c4 * 4)
                                  : (B + (long)(col0 + r) * ldb + kk + c4 * 4);
            uint32_t dst = smb + 4u * (uint32_t)(s * STG + (isA ? 0 : BM * RS) + r * RS + c4 * 4);
            asm volatile("cp.async.cg.shared.global [%0], [%1], 16;" :: "r"(dst), "l"(gp));
        }
    };

    // prologue
    #pragma unroll
    for (int s = 0; s < NST - 1; s++) {
        if (s < nch) copy_stage(s, s);
        asm volatile("cp.async.commit_group;" ::: "memory");
    }

    const int ar = wm * 32 + (lane >> 2);      // A row within CTA tile
    const int ac = lane & 3;                   // k sub-col
    const int br = wn * WN + (lane >> 2);      // B row within CTA tile

    for (int c = 0; c < nch; c++) {
        if (c + NST - 1 < nch) copy_stage((c + NST - 1) % NST, c + NST - 1);
        asm volatile("cp.async.commit_group;" ::: "memory");
        asm volatile("cp.async.wait_group %0;" :: "n"(NST - 2) : "memory");
        __syncthreads();

        const float* As = sm + (c % NST) * STG;
        const float* Bs = As + BM * RS;

        #pragma unroll
        for (int ks = 0; ks < 4; ks++) {
            uint32_t Ahi[MT][4], Alo[MT][4];
            #pragma unroll
            for (int mt = 0; mt < MT; mt++) {
                const float* ap = As + (ar + mt * 16) * RS + ks * 8 + ac;
                split_tf32(ap[0],          Ahi[mt][0], Alo[mt][0]);
                split_tf32(ap[8 * RS],     Ahi[mt][1], Alo[mt][1]);
                split_tf32(ap[4],          Ahi[mt][2], Alo[mt][2]);
                split_tf32(ap[8 * RS + 4], Ahi[mt][3], Alo[mt][3]);
            }
            uint32_t Bhi[NT][2], Blo[NT][2];
            #pragma unroll
            for (int nt = 0; nt < NT; nt++) {
                const float* bp = Bs + (br + nt * 8) * RS + ks * 8 + ac;
                split_tf32(bp[0], Bhi[nt][0], Blo[nt][0]);
                split_tf32(bp[4], Bhi[nt][1], Blo[nt][1]);
            }
            #pragma unroll
            for (int mt = 0; mt < MT; mt++)
                #pragma unroll
                for (int nt = 0; nt < NT; nt++) {
                    mma_tf32(acc[mt][nt], Ahi[mt], Bhi[nt]);
                    mma_tf32(acc[mt][nt], Ahi[mt], Blo[nt]);
                    mma_tf32(acc[mt][nt], Alo[mt], Bhi[nt]);
                }
        }
        __syncthreads();
    }

    // epilogue
    const int rbase = row0 + wm * 32 + (lane >> 2);
    const int cbase = col0 + wn * WN + (lane & 3) * 2;
    #pragma unroll
    for (int mt = 0; mt < MT; mt++) {
        #pragma unroll
        for (int half = 0; half < 2; half++) {
            const long gm = rbase + mt * 16 + half * 8;
            float* crow = C + gm * ldc;
            #pragma unroll
            for (int nt = 0; nt < NT; nt++) {
                const int gn = cbase + nt * 8;
                float v0 = acc[mt][nt][half * 2 + 0] * alpha;
                float v1 = acc[mt][nt][half * 2 + 1] * alpha;
                if (EXP_)  { v0 = expf(v0); v1 = expf(v1); }
                if (BIAS_) { v0 += bias[gn]; v1 += bias[gn + 1]; }
                if (RELU_) { v0 = fmaxf(v0, 0.f); v1 = fmaxf(v1, 0.f); }
                float2 o; o.x = v0; o.y = v1;
                *(float2*)(crow + gn) = o;
            }
        }
    }
}

// ---------------- tiled transpose: out[z][c][r] = in[z][r][c] (* scale[z][r]) -----
template<bool SC>
__global__ void transpose_k(const float* __restrict__ in, float* __restrict__ out,
                            const float* __restrict__ scale,
                            int R, int C, int ldin, int ldout,
                            long inS1, long inS2, int zdiv)
{
    __shared__ float tile[32][33];
    const int z = blockIdx.z;
    in  += (long)(z / zdiv) * inS1 + (long)(z % zdiv) * inS2;
    out += (long)z * (long)C * ldout;
    if (SC) scale += (long)z * R;
    const int c0 = blockIdx.x * 32, r0 = blockIdx.y * 32;
    const int tx = threadIdx.x, ty = threadIdx.y;
    #pragma unroll
    for (int i = ty; i < 32; i += 8) {
        float v = in[(long)(r0 + i) * ldin + c0 + tx];
        if (SC) v *= scale[r0 + i];
        tile[i][tx] = v;
    }
    __syncthreads();
    #pragma unroll
    for (int i = ty; i < 32; i += 8)
        out[(long)(c0 + i) * ldout + r0 + tx] = tile[tx][i];
}

// -------- deterministic per-column (query-axis) softmax denominator --------------
__global__ void colsum_inv(const float* __restrict__ S, float* __restrict__ dinv) {
    const int z = blockIdx.y;
    const int s = blockIdx.x * 256 + threadIdx.x;
    const float* p = S + (long)z * 1048576 + s;
    float acc = 0.f;
    #pragma unroll 8
    for (int t = 0; t < 1024; t++) acc += p[(long)t * 1024];
    dinv[z * 1024 + s] = 1.f / acc;
}

// ---------------- reductions + sub_norm -------------------------------------------
__device__ __forceinline__ float blockReduceSum(float v) {
    __shared__ float sh[32];
    __syncthreads();
    int lane = threadIdx.x & 31, wid = threadIdx.x >> 5;
    #pragma unroll
    for (int o = 16; o; o >>= 1) v += __shfl_xor_sync(0xffffffffu, v, o);
    if (lane == 0) sh[wid] = v;
    __syncthreads();
    if (wid == 0) {
        v = (threadIdx.x < (blockDim.x >> 5)) ? sh[lane] : 0.f;
        #pragma unroll
        for (int o = 16; o; o >>= 1) v += __shfl_xor_sync(0xffffffffu, v, o);
        if (lane == 0) sh[0] = v;
    }
    __syncthreads();
    return sh[0];
}

__global__ void add_subnorm(const float* __restrict__ A, const float* __restrict__ R,
                            float* __restrict__ O) {
    long base = (long)blockIdx.x * 1024;
    int t = threadIdx.x;
    float v[4];
    float s = 0.f;
    #pragma unroll
    for (int j = 0; j < 4; j++) { v[j] = A[base + t + j * 256] + R[base + t + j * 256]; s += v[j]; }
    s = blockReduceSum(s);
    float mean = s * (1.f / 1024.f);
    float q = 0.f;
    #pragma unroll
    for (int j = 0; j < 4; j++) { float d = v[j] - mean; q += d * d; }
    q = blockReduceSum(q);
    float sd = sqrtf(q * (1.f / 1023.f));
    #pragma unroll
    for (int j = 0; j < 4; j++) O[base + t + j * 256] = v[j] - mean - sd;
}

// ---------------- host --------------------------------------------------------------
static const int SMB128 = 3 * (128 + 128) * 36 * 4;   // 110,592 B
static const int SMB64  = 3 * (128 +  64) * 36 * 4;   //  82,944 B

extern "C" void kernel_launch(void* const* d_in, const int* in_sizes, int n_in,
                              void* d_out, int out_size) {
    const float* x    = (const float*)d_in[0];
    const float* y    = (const float*)d_in[1];
    const float* Wq1  = (const float*)d_in[2];
    const float* Wk1  = (const float*)d_in[3];
    const float* Wv1  = (const float*)d_in[4];
    const float* Wo1  = (const float*)d_in[5];
    const float* Wq2  = (const float*)d_in[6];
    const float* Wk2  = (const float*)d_in[7];
    const float* Wv2  = (const float*)d_in[8];
    const float* Wo2  = (const float*)d_in[9];
    const float* W_in = (const float*)d_in[10];
    const float* b_in = (const float*)d_in[11];
    const float* W_out= (const float*)d_in[12];
    const float* b_out= (const float*)d_in[13];
    float* out = (float*)d_out;

    float *Wt0, *Wt1, *Wt2, *WoT, *Q, *K, *V, *Vt, *S, *dinv, *P, *M, *o1, *o2, *hid, *ff;
    cudaGetSymbolAddress((void**)&Wt0, g_Wt0);
    cudaGetSymbolAddress((void**)&Wt1, g_Wt1);
    cudaGetSymbolAddress((void**)&Wt2, g_Wt2);
    cudaGetSymbolAddress((void**)&WoT, g_WoT);
    cudaGetSymbolAddress((void**)&Q,   g_Q);
    cudaGetSymbolAddress((void**)&K,   g_K);
    cudaGetSymbolAddress((void**)&V,   g_V);
    cudaGetSymbolAddress((void**)&Vt,  g_Vt);
    cudaGetSymbolAddress((void**)&S,   g_S);
    cudaGetSymbolAddress((void**)&dinv,g_dinv);
    cudaGetSymbolAddress((void**)&P,   g_P);
    cudaGetSymbolAddress((void**)&M,   g_M);
    cudaGetSymbolAddress((void**)&o1,  g_o1);
    cudaGetSymbolAddress((void**)&o2,  g_o2);
    cudaGetSymbolAddress((void**)&hid, g_hid);
    cudaGetSymbolAddress((void**)&ff,  g_ff);

    cudaFuncSetAttribute(mma_gemm<128,false,false,false>, cudaFuncAttributeMaxDynamicSharedMemorySize, SMB128);
    cudaFuncSetAttribute(mma_gemm<128,false,false,true >, cudaFuncAttributeMaxDynamicSharedMemorySize, SMB128);
    cudaFuncSetAttribute(mma_gemm<64 ,false,false,false>, cudaFuncAttributeMaxDynamicSharedMemorySize, SMB64);
    cudaFuncSetAttribute(mma_gemm<128,true ,true ,false>, cudaFuncAttributeMaxDynamicSharedMemorySize, SMB128);
    cudaFuncSetAttribute(mma_gemm<128,true ,false,false>, cudaFuncAttributeMaxDynamicSharedMemorySize, SMB128);

    dim3 blkT(32, 8);
    const long Z0 = 0;

    auto run_mha = [&](const float* qsrc, const float* kvsrc,
                       const float* Wq, const float* Wk, const float* Wv, const float* Wo,
                       const float* resid, float* obuf) {
        // repack per-head weights (H,D,dk) -> [(h,k), d]
        dim3 gw(2, 32, HH);
        transpose_k<false><<<gw, blkT>>>(Wq, Wt0, nullptr, 1024, 64, 64, 1024, 65536, 0, 1);
        transpose_k<false><<<gw, blkT>>>(Wk, Wt1, nullptr, 1024, 64, 64, 1024, 65536, 0, 1);
        transpose_k<false><<<gw, blkT>>>(Wv, Wt2, nullptr, 1024, 64, 64, 1024, 65536, 0, 1);

        // projections: (4096,1024) x (1024,1024)^T
        dim3 gp(8, 32, 1);
        mma_gemm<128,false,false,false><<<gp, 256, SMB128>>>(
            qsrc, Wt0, nullptr, Q, 1024, 1024, 1024, 1024, Z0,Z0,Z0,Z0,Z0,Z0, 1, 1.f);
        mma_gemm<128,false,false,false><<<gp, 256, SMB128>>>(
            kvsrc, Wt1, nullptr, K, 1024, 1024, 1024, 1024, Z0,Z0,Z0,Z0,Z0,Z0, 1, 1.f);
        mma_gemm<128,false,false,false><<<gp, 256, SMB128>>>(
            kvsrc, Wt2, nullptr, V, 1024, 1024, 1024, 1024, Z0,Z0,Z0,Z0,Z0,Z0, 1, 1.f);

        // scores: S[(b,h), t, s] = exp( Q.K^T / 8 )
        dim3 gs(8, 8, BB * HH);
        mma_gemm<128,false,false,true><<<gs, 256, SMB128>>>(
            Q, K, nullptr, S, 64, 1024, 1024, 1024,
            1048576, 64, 1048576, 64, 16777216, 1048576, HH, 0.125f);

        // softmax denominator over query axis t (deterministic column sums)
        colsum_inv<<<dim3(4, BB * HH), 256>>>(S, dinv);

        // V transpose + fold dinv: Vt[(b,h), v, s] = V[b, s, (h,v)] * dinv[(b,h), s]
        dim3 gv(2, 32, BB * HH);
        transpose_k<true><<<gv, blkT>>>(V, Vt, dinv, 1024, 64, 1024, 1024, 1048576, 64, HH);

        // partial: P[b, t, (h,v)] = sum_s expS[t,s] * Vt'[v,s]
        dim3 gpp(1, 8, BB * HH);
        mma_gemm<64,false,false,false><<<gpp, 256, SMB64>>>(
            S, Vt, nullptr, P, 1024, 1024, 1024, 1024,
            16777216, 1048576, 1048576, 65536, 1048576, 64, HH, 1.f);

        // output projection
        dim3 gwo(32, 32, 1);
        transpose_k<false><<<gwo, blkT>>>(Wo, WoT, nullptr, 1024, 1024, 1024, 1024, Z0, Z0, 1);
        mma_gemm<128,false,false,false><<<gp, 256, SMB128>>>(
            P, WoT, nullptr, M, 1024, 1024, 1024, 1024, Z0,Z0,Z0,Z0,Z0,Z0, 1, 1.f);

        add_subnorm<<<BB * TT, 256>>>(M, resid, obuf);
    };

    // out1 = sub_norm(mha(y,y,y) + y)
    run_mha(y, y, Wq1, Wk1, Wv1, Wo1, y, o1);
    // out2 = sub_norm(mha(y,x,x) + out1)
    run_mha(y, x, Wq2, Wk2, Wv2, Wo2, o1, o2);

    // FFN on y: hid = relu(y @ W_in^T + b_in); ff = hid @ W_out^T + b_out
    dim3 gf1(32, 32, 1);
    mma_gemm<128,true,true,false><<<gf1, 256, SMB128>>>(
        y, W_in, b_in, hid, 1024, 1024, 1024, 4096, Z0,Z0,Z0,Z0,Z0,Z0, 1, 1.f);
    dim3 gf2(8, 32, 1);
    mma_gemm<128,true,false,false><<<gf2, 256, SMB128>>>(
        hid, W_out, b_out, ff, 4096, 4096, 4096, 1024, Z0,Z0,Z0,Z0,Z0,Z0, 1, 1.f);

    add_subnorm<<<BB * TT, 256>>>(ff, o2, out);
}